// round 16
// baseline (speedup 1.0000x reference)
#include <cuda_runtime.h>
#include <cstdint>

#define BB 4
#define NN 4096
#define CC 128
#define NROWS (BB*NN)       // 16384
#define NCHUNK 64           // 64-row chunks per batch
#define TOTCHUNK (BB*NCHUNK)  // 256
#define XS_STRIDE 132
#define BSTRIDE 132

typedef unsigned long long u64;
__device__ __forceinline__ u64 pack2(float x, float y) {
    u64 r; asm("mov.b64 %0, {%1, %2};" : "=l"(r) : "f"(x), "f"(y)); return r;
}
__device__ __forceinline__ void unpack2(u64 v, float& x, float& y) {
    asm("mov.b64 {%0, %1}, %2;" : "=f"(x), "=f"(y) : "l"(v));
}
__device__ __forceinline__ u64 ffma2(u64 a, u64 b, u64 c) {
    u64 d; asm("fma.rn.f32x2 %0, %1, %2, %3;" : "=l"(d) : "l"(a), "l"(b), "l"(c)); return d;
}

// ---- scratch (device globals) ----
__device__ float  g_Q [NROWS*CC];
__device__ float  g_K [NROWS*CC];
__device__ float  g_qnorm[NROWS];
__device__ float  g_knorm[NROWS];
__device__ float  g_Gpart[(size_t)TOTCHUNK*CC*CC];
__device__ double g_spart[TOTCHUNK*CC];
__device__ float  g_Mfin[BB*CC*CC];
__device__ double g_s[BB*CC];
__device__ float  g_sf[BB*CC];
__device__ double g_den[NROWS];
__device__ int    g_flag[NROWS];
__device__ int    g_bcount[BB];
__device__ int    g_list[BB*256];
__device__ double g_bpart[BB*256*32];

// ============================================================
// projkv: fused projection + (for k) G/s partial computation.
// bid&1 == 0: q leg (project, store g_Q, qnorm).
// bid&1 == 1: k leg (project, store g_K, knorm, then K̂->smem and
//             two 64-row chunk GEMMs G = K̂^T V + s partials,
//             bit-identical to the old kv_kernel arithmetic).
// smem: phase1 Xs[32][132]+Wc[32][132] (33.8KB) union with
//       phase2 Kt[128][128] (64KB) + Vs[64][128] (32KB) = 96KB.
// ============================================================
#define PK_SMEM ((128*128 + 64*128) * 4)   // 98304 bytes

__global__ void __launch_bounds__(256) projkv_kernel(
    const float* __restrict__ q_in, const float* __restrict__ k_in,
    const float* __restrict__ v_in, const float* __restrict__ W,
    const float* __restrict__ bias)
{
    extern __shared__ float smd[];
    float* Xs = smd;
    float* Wc = smd + 32*XS_STRIDE;

    const int tid = threadIdx.x;
    const int tx  = tid & 15;
    const int ty  = tid >> 4;
    const int bid = blockIdx.x;
    const int z   = bid & 1;                 // interleave q/k for SM balance
    const int row0 = (bid >> 1) * 128;
    const float* X = z ? k_in : q_in;

    u64 acc2[8][4];
    #pragma unroll
    for (int i = 0; i < 8; i++)
        #pragma unroll
        for (int jp = 0; jp < 4; jp++) acc2[i][jp] = 0ULL;

    for (int c0 = 0; c0 < CC; c0 += 32) {
        __syncthreads();
        for (int t = tid; t < 128*8; t += 256) {
            int r = t >> 3, cg = t & 7;
            float4 v = *(const float4*)(X + (size_t)(row0 + r)*CC + c0 + cg*4);
            Xs[(cg*4+0)*XS_STRIDE + r] = v.x;
            Xs[(cg*4+1)*XS_STRIDE + r] = v.y;
            Xs[(cg*4+2)*XS_STRIDE + r] = v.z;
            Xs[(cg*4+3)*XS_STRIDE + r] = v.w;
        }
        for (int t = tid; t < 128*8; t += 256) {
            int d = t >> 3, cg = t & 7;
            float4 w = *(const float4*)(W + (size_t)d*CC + c0 + cg*4);
            Wc[(cg*4+0)*XS_STRIDE + d] = w.x;
            Wc[(cg*4+1)*XS_STRIDE + d] = w.y;
            Wc[(cg*4+2)*XS_STRIDE + d] = w.z;
            Wc[(cg*4+3)*XS_STRIDE + d] = w.w;
        }
        __syncthreads();
        #pragma unroll 4
        for (int kk = 0; kk < 32; kk++) {
            float a[8];
            *(float4*)&a[0] = *(float4*)&Xs[kk*XS_STRIDE + ty*8];
            *(float4*)&a[4] = *(float4*)&Xs[kk*XS_STRIDE + ty*8 + 4];
            const ulonglong2 bv0 = *(ulonglong2*)&Wc[kk*XS_STRIDE + tx*8];
            const ulonglong2 bv1 = *(ulonglong2*)&Wc[kk*XS_STRIDE + tx*8 + 4];
            u64 b2[4] = {bv0.x, bv0.y, bv1.x, bv1.y};
            #pragma unroll
            for (int i = 0; i < 8; i++) {
                const u64 as = pack2(a[i], a[i]);
                #pragma unroll
                for (int jp = 0; jp < 4; jp++)
                    acc2[i][jp] = ffma2(as, b2[jp], acc2[i][jp]);
            }
        }
    }

    float acc[8][8];
    #pragma unroll
    for (int i = 0; i < 8; i++)
        #pragma unroll
        for (int jp = 0; jp < 4; jp++)
            unpack2(acc2[i][jp], acc[i][2*jp], acc[i][2*jp+1]);

    float bj[8];
    *(float4*)&bj[0] = *(const float4*)&bias[tx*8];
    *(float4*)&bj[4] = *(const float4*)&bias[tx*8 + 4];
    #pragma unroll
    for (int i = 0; i < 8; i++)
        #pragma unroll
        for (int j = 0; j < 8; j++) acc[i][j] += bj[j];

    float nrm[8];
    #pragma unroll
    for (int i = 0; i < 8; i++) {
        float sq = 0.f;
        #pragma unroll
        for (int j = 0; j < 8; j++) sq = fmaf(acc[i][j], acc[i][j], sq);
        #pragma unroll
        for (int off = 8; off; off >>= 1)
            sq += __shfl_xor_sync(0xffffffffu, sq, off, 16);
        nrm[i] = sqrtf(sq);
        if (tx == 0) {
            if (z == 0) g_qnorm[row0 + ty*8 + i] = nrm[i];
            else        g_knorm[row0 + ty*8 + i] = nrm[i];
        }
    }

    if (z == 0) {
        #pragma unroll
        for (int i = 0; i < 8; i++) {
            const size_t off = (size_t)(row0 + ty*8 + i)*CC + tx*8;
            *(float4*)(g_Q + off)     = *(float4*)&acc[i][0];
            *(float4*)(g_Q + off + 4) = *(float4*)&acc[i][4];
        }
        return;
    }

    // k leg: store raw K, then K̂ into smem (same fp32 bits as the
    // old g_Kh store: acc * (1/nrm)).
    float* Kt = smd;               // [128][128]
    float* Vs = smd + 128*128;     // [64][128]

    #pragma unroll
    for (int i = 0; i < 8; i++) {
        const size_t off = (size_t)(row0 + ty*8 + i)*CC + tx*8;
        *(float4*)(g_K + off)     = *(float4*)&acc[i][0];
        *(float4*)(g_K + off + 4) = *(float4*)&acc[i][4];
    }
    __syncthreads();   // phase-1 smem reads complete before overwrite
    #pragma unroll
    for (int i = 0; i < 8; i++) {
        const float inv = 1.f / nrm[i];
        float4 o0, o1;
        o0.x = acc[i][0]*inv; o0.y = acc[i][1]*inv;
        o0.z = acc[i][2]*inv; o0.w = acc[i][3]*inv;
        o1.x = acc[i][4]*inv; o1.y = acc[i][5]*inv;
        o1.z = acc[i][6]*inv; o1.w = acc[i][7]*inv;
        *(float4*)&Kt[(ty*8 + i)*CC + tx*8]     = o0;
        *(float4*)&Kt[(ty*8 + i)*CC + tx*8 + 4] = o1;
    }
    __syncthreads();

    // two 64-row chunks: G = K̂^T V, s partials (kv-identical order)
    #pragma unroll
    for (int sub = 0; sub < 2; sub++) {
        const int blk = (row0 >> 6) + sub;     // global chunk index
        const float4* V4 = (const float4*)(v_in + (size_t)(row0 + sub*64)*CC);
        for (int t = tid; t < 64*CC/4; t += 256)
            ((float4*)Vs)[t] = V4[t];
        __syncthreads();

        u64 gacc[8][4];
        #pragma unroll
        for (int i = 0; i < 8; i++)
            #pragma unroll
            for (int jp = 0; jp < 4; jp++) gacc[i][jp] = 0ULL;

        const float* Ks = Kt + sub*64*CC;
        #pragma unroll 4
        for (int n = 0; n < 64; n++) {
            float a[8];
            *(float4*)&a[0] = *(float4*)&Ks[n*CC + ty*8];
            *(float4*)&a[4] = *(float4*)&Ks[n*CC + ty*8 + 4];
            const ulonglong2 bv0 = *(ulonglong2*)&Vs[n*CC + tx*8];
            const ulonglong2 bv1 = *(ulonglong2*)&Vs[n*CC + tx*8 + 4];
            u64 b2[4] = {bv0.x, bv0.y, bv1.x, bv1.y};
            #pragma unroll
            for (int i = 0; i < 8; i++) {
                const u64 as = pack2(a[i], a[i]);
                #pragma unroll
                for (int jp = 0; jp < 4; jp++)
                    gacc[i][jp] = ffma2(as, b2[jp], gacc[i][jp]);
            }
        }

        if (tid < 128) {
            double s0 = 0.0, s1 = 0.0, s2 = 0.0, s3 = 0.0;
            #pragma unroll 4
            for (int n = 0; n < 64; n += 4) {
                s0 += (double)Ks[(n+0)*CC + tid];
                s1 += (double)Ks[(n+1)*CC + tid];
                s2 += (double)Ks[(n+2)*CC + tid];
                s3 += (double)Ks[(n+3)*CC + tid];
            }
            g_spart[blk*CC + tid] = (s0 + s1) + (s2 + s3);
        }

        float* Gp = g_Gpart + (size_t)blk*CC*CC;
        #pragma unroll
        for (int i = 0; i < 8; i++) {
            float ga[8];
            #pragma unroll
            for (int jp = 0; jp < 4; jp++)
                unpack2(gacc[i][jp], ga[2*jp], ga[2*jp+1]);
            float* grow = Gp + (size_t)(ty*8 + i)*CC + tx*8;
            *(float4*)grow       = *(float4*)&ga[0];
            *(float4*)(grow + 4) = *(float4*)&ga[4];
        }
        __syncthreads();   // before Vs is overwritten next sub
    }
}

// ============================================================
// redmk (fused reduce + mk): grid 64 = (4 batches x 8-row chunks).
// ============================================================
#define RM_SMEM ((128*XS_STRIDE + 8*128 + 128) * 4 + 64*8 + 8*8)
__global__ void __launch_bounds__(256, 1) redmk_kernel(
    const float* __restrict__ W, const float* __restrict__ bias)
{
    extern __shared__ float sm[];
    float*  Wt   = sm;
    float*  Gs   = sm + 128*XS_STRIDE;
    float*  sb   = Gs + 8*128;
    double* sred = (double*)(sb + 128);
    double* sfin = sred + 64;

    const int tid = threadIdx.x;
    const int b   = blockIdx.x >> 4;
    const int c0  = (blockIdx.x & 15) * 8;

    {
        const int r  = tid >> 5;
        const int e4 = tid & 31;
        const int c  = c0 + r;
        float4 a0 = make_float4(0.f,0.f,0.f,0.f), a1 = a0, a2 = a0, a3 = a0;
        #pragma unroll 4
        for (int p = 0; p < NCHUNK; p += 4) {
            const size_t base = ((size_t)((b << 6) + p)) << 14;
            const size_t eoff = ((size_t)c << 7) + (e4 << 2);
            const float4 v0 = *(const float4*)&g_Gpart[base            + eoff];
            const float4 v1 = *(const float4*)&g_Gpart[base + (1u<<14) + eoff];
            const float4 v2 = *(const float4*)&g_Gpart[base + (2u<<14) + eoff];
            const float4 v3 = *(const float4*)&g_Gpart[base + (3u<<14) + eoff];
            a0.x += v0.x; a0.y += v0.y; a0.z += v0.z; a0.w += v0.w;
            a1.x += v1.x; a1.y += v1.y; a1.z += v1.z; a1.w += v1.w;
            a2.x += v2.x; a2.y += v2.y; a2.z += v2.z; a2.w += v2.w;
            a3.x += v3.x; a3.y += v3.y; a3.z += v3.z; a3.w += v3.w;
        }
        float4 a;
        a.x = (a0.x + a1.x) + (a2.x + a3.x);
        a.y = (a0.y + a1.y) + (a2.y + a3.y);
        a.z = (a0.z + a1.z) + (a2.z + a3.z);
        a.w = (a0.w + a1.w) + (a2.w + a3.w);
        *(float4*)&Gs[r*128 + e4*4] = a;
    }

    if (tid < 64) {
        const int cidx = tid >> 3;
        const int pg   = tid & 7;
        const int c    = c0 + cidx;
        double s = 0.0;
        #pragma unroll
        for (int j = 0; j < 8; j++)
            s += g_spart[((b << 6) + pg*8 + j)*CC + c];
        sred[cidx*8 + pg] = s;
    }

    for (int i = tid; i < CC*CC; i += 256) {
        int d = i >> 7, e = i & 127;
        Wt[e*XS_STRIDE + d] = W[i];
    }
    if (tid < 128) sb[tid] = bias[tid];
    __syncthreads();

    if (tid < 8) {
        double s = 0.0;
        #pragma unroll
        for (int pg = 0; pg < 8; pg++) s += sred[tid*8 + pg];
        sfin[tid] = s;
        g_s [b*CC + c0 + tid] = s;
        g_sf[b*CC + c0 + tid] = (float)s;
    }
    __syncthreads();

    if (tid < 128) {
        const int r  = tid >> 4;
        const int dg = tid & 15;
        float acc[8] = {};
        #pragma unroll 4
        for (int e = 0; e < 128; e++) {
            const float a = Gs[r*128 + e];
            float bb[8];
            *(float4*)&bb[0] = *(float4*)&Wt[e*XS_STRIDE + dg*8];
            *(float4*)&bb[4] = *(float4*)&Wt[e*XS_STRIDE + dg*8 + 4];
            #pragma unroll
            for (int j = 0; j < 8; j++)
                acc[j] = fmaf(a, bb[j], acc[j]);
        }
        const float sc = (float)sfin[r];
        float4 o0, o1;
        o0.x = fmaf(sc, sb[dg*8+0], acc[0]);
        o0.y = fmaf(sc, sb[dg*8+1], acc[1]);
        o0.z = fmaf(sc, sb[dg*8+2], acc[2]);
        o0.w = fmaf(sc, sb[dg*8+3], acc[3]);
        o1.x = fmaf(sc, sb[dg*8+4], acc[4]);
        o1.y = fmaf(sc, sb[dg*8+5], acc[5]);
        o1.z = fmaf(sc, sb[dg*8+6], acc[6]);
        o1.w = fmaf(sc, sb[dg*8+7], acc[7]);
        float* mrow = g_Mfin + (size_t)b*CC*CC + (size_t)(c0 + r)*CC + dg*8;
        *(float4*)mrow       = o0;
        *(float4*)(mrow + 4) = o1;
    }
}

// ============================================================
// den (fp32): den = q . s ; flag |den|/qn < 2.
// ============================================================
__global__ void __launch_bounds__(256) den_kernel()
{
    const int w = (blockIdx.x << 3) + (threadIdx.x >> 5);
    const int lane = threadIdx.x & 31;
    const int b = w >> 12;
    const float* qr = g_Q + (size_t)w*CC;
    const float* s  = g_sf + b*CC;
    float a0 = qr[lane      ] * s[lane      ];
    float a1 = qr[lane +  32] * s[lane +  32];
    float a2 = qr[lane +  64] * s[lane +  64];
    float a3 = qr[lane +  96] * s[lane +  96];
    float acc = (a0 + a1) + (a2 + a3);
    #pragma unroll
    for (int off = 16; off; off >>= 1)
        acc += __shfl_xor_sync(0xffffffffu, acc, off);
    if (lane == 0) {
        const float qn = g_qnorm[w];
        g_den[w] = (double)acc + 1e-8 * (double)qn;
        g_flag[w] = (fabsf(acc / qn) < 2.0f) ? 1 : 0;
    }
}

// ============================================================
__global__ void __launch_bounds__(256) compact_kernel()
{
    __shared__ int cnt[256];
    __shared__ int offs[256];
    const int t = threadIdx.x;
    for (int b = 0; b < BB; b++) {
        const int base = b*NN + t*(NN/256);
        int c = 0;
        #pragma unroll
        for (int i = 0; i < NN/256; i++) c += g_flag[base + i];
        cnt[t] = c;
        __syncthreads();
        if (t == 0) {
            int run = 0;
            for (int u = 0; u < 256; u++) { offs[u] = run; run += cnt[u]; }
            g_bcount[b] = run < 256 ? run : 256;
        }
        __syncthreads();
        int o = offs[t];
        #pragma unroll
        for (int i = 0; i < NN/256; i++) {
            const int row = base + i;
            if (g_flag[row]) {
                if (o < 256) { g_list[b*256 + o] = row; g_flag[row] = b*256 + o + 1; }
                else         { g_flag[row] = 0; }
                o++;
            }
        }
        __syncthreads();
    }
}

// ============================================================
// brute: reference-replica den GEMM for flagged rows.
// ============================================================
__global__ void __launch_bounds__(256, 1) brute_kernel()
{
    extern __shared__ float sm[];
    float* Qs  = sm;
    float* Kst = sm + 128*BSTRIDE;
    __shared__ float qn_s[128], kn_s[128];

    const int chunk = blockIdx.x;
    const int b     = blockIdx.y;
    const int tile  = blockIdx.z;
    int cnt = g_bcount[b] - tile*128;
    if (cnt <= 0) return;
    if (cnt > 128) cnt = 128;

    const int tid = threadIdx.x;
    const int tx  = tid & 15;
    const int ty  = tid >> 4;
    const int wid = tid >> 5;
    const int lane = tid & 31;
    const int key0 = b*NN + chunk*128;

    for (int t = tid; t < 128*BSTRIDE; t += 256) Qs[t] = 0.f;
    __syncthreads();

    for (int r = wid; r < cnt; r += 8) {
        const int row = g_list[b*256 + tile*128 + r];
        const float* qr = g_Q + (size_t)row*CC;
        #pragma unroll
        for (int u = 0; u < 4; u++) {
            const int c = lane + u*32;
            Qs[c*BSTRIDE + r] = qr[c];
        }
        if (lane == 0) qn_s[r] = g_qnorm[row];
    }
    for (int r = cnt + tid; r < 128; r += 256) qn_s[r] = 1.f;

    for (int r = wid; r < 128; r += 8) {
        const float* kr = g_K + (size_t)(key0 + r)*CC;
        #pragma unroll
        for (int u = 0; u < 4; u++) {
            const int c = lane + u*32;
            Kst[c*BSTRIDE + r] = kr[c];
        }
        if (lane == 0) kn_s[r] = g_knorm[key0 + r];
    }
    __syncthreads();

    u64 acc2[8][4];
    #pragma unroll
    for (int i = 0; i < 8; i++)
        #pragma unroll
        for (int jp = 0; jp < 4; jp++) acc2[i][jp] = 0ULL;

    #pragma unroll 4
    for (int c = 0; c < 128; c++) {
        float a[8];
        *(float4*)&a[0] = *(float4*)&Qs[c*BSTRIDE + ty*8];
        *(float4*)&a[4] = *(float4*)&Qs[c*BSTRIDE + ty*8 + 4];
        const ulonglong2 bv0 = *(ulonglong2*)&Kst[c*BSTRIDE + tx*8];
        const ulonglong2 bv1 = *(ulonglong2*)&Kst[c*BSTRIDE + tx*8 + 4];
        u64 b2[4] = {bv0.x, bv0.y, bv1.x, bv1.y};
        #pragma unroll
        for (int i = 0; i < 8; i++) {
            const u64 as = pack2(a[i], a[i]);
            #pragma unroll
            for (int jp = 0; jp < 4; jp++)
                acc2[i][jp] = ffma2(as, b2[jp], acc2[i][jp]);
        }
    }

    #pragma unroll
    for (int i = 0; i < 8; i++) {
        float acc[8];
        #pragma unroll
        for (int jp = 0; jp < 4; jp++)
            unpack2(acc2[i][jp], acc[2*jp], acc[2*jp+1]);
        const float qn = qn_s[ty*8 + i];
        double dsum = 0.0;
        #pragma unroll
        for (int j = 0; j < 8; j++) {
            const float d = qn * kn_s[tx*8 + j] + 1e-8f;
            dsum += (double)(acc[j] / d);
        }
        #pragma unroll
        for (int off = 8; off; off >>= 1)
            dsum += __shfl_xor_sync(0xffffffffu, dsum, off, 16);
        if (tx == 0)
            g_bpart[((size_t)(b*256 + tile*128 + ty*8 + i))*32 + chunk] = dsum;
    }
}

// ============================================================
// out = (q @ M) / den; combine folded in.
// ============================================================
__global__ void __launch_bounds__(256, 2) out_kernel(float* __restrict__ out)
{
    extern __shared__ float sm[];
    float* Ms = sm;
    float* Xs = sm + CC*CC;

    const int tid = threadIdx.x;
    const int tx  = tid & 15;
    const int ty  = tid >> 4;
    const int b   = blockIdx.x >> 5;
    const int row0 = blockIdx.x * 128;

    const float4* M4 = (const float4*)(g_Mfin + (size_t)b*CC*CC);
    for (int t = tid; t < 4096; t += 256) ((float4*)Ms)[t] = M4[t];

    u64 acc2[8][4];
    #pragma unroll
    for (int i = 0; i < 8; i++)
        #pragma unroll
        for (int jp = 0; jp < 4; jp++) acc2[i][jp] = 0ULL;

    for (int c0 = 0; c0 < CC; c0 += 32) {
        __syncthreads();
        for (int t = tid; t < 128*8; t += 256) {
            int r = t >> 3, cg = t & 7;
            float4 v = *(const float4*)(g_Q + (size_t)(row0 + r)*CC + c0 + cg*4);
            Xs[(cg*4+0)*XS_STRIDE + r] = v.x;
            Xs[(cg*4+1)*XS_STRIDE + r] = v.y;
            Xs[(cg*4+2)*XS_STRIDE + r] = v.z;
            Xs[(cg*4+3)*XS_STRIDE + r] = v.w;
        }
        __syncthreads();
        #pragma unroll 4
        for (int kk = 0; kk < 32; kk++) {
            float a[8];
            *(float4*)&a[0] = *(float4*)&Xs[kk*XS_STRIDE + ty*8];
            *(float4*)&a[4] = *(float4*)&Xs[kk*XS_STRIDE + ty*8 + 4];
            const ulonglong2 bv0 = *(ulonglong2*)&Ms[(c0+kk)*CC + tx*8];
            const ulonglong2 bv1 = *(ulonglong2*)&Ms[(c0+kk)*CC + tx*8 + 4];
            u64 b2[4] = {bv0.x, bv0.y, bv1.x, bv1.y};
            #pragma unroll
            for (int i = 0; i < 8; i++) {
                const u64 as = pack2(a[i], a[i]);
                #pragma unroll
                for (int jp = 0; jp < 4; jp++)
                    acc2[i][jp] = ffma2(as, b2[jp], acc2[i][jp]);
            }
        }
    }

    #pragma unroll
    for (int i = 0; i < 8; i++) {
        float acc[8];
        #pragma unroll
        for (int jp = 0; jp < 4; jp++)
            unpack2(acc2[i][jp], acc[2*jp], acc[2*jp+1]);
        const int row = row0 + ty*8 + i;
        const int fl = g_flag[row];
        double den;
        if (fl > 0) {
            const int slot = fl - 1;
            double s = 0.0;
            #pragma unroll
            for (int c = 0; c < 32; c++)
                s += g_bpart[(size_t)slot*32 + c];
            den = (double)g_qnorm[row] * (s + 1e-8);
        } else {
            den = g_den[row];
        }
        const double inv = 1.0 / den;
        float4 o0, o1;
        o0.x = (float)(acc[0]*inv); o0.y = (float)(acc[1]*inv);
        o0.z = (float)(acc[2]*inv); o0.w = (float)(acc[3]*inv);
        o1.x = (float)(acc[4]*inv); o1.y = (float)(acc[5]*inv);
        o1.z = (float)(acc[6]*inv); o1.w = (float)(acc[7]*inv);
        float* orow = out + (size_t)row*CC + tx*8;
        *(float4*)orow       = o0;
        *(float4*)(orow + 4) = o1;
    }
}

// ============================================================
extern "C" void kernel_launch(void* const* d_in, const int* in_sizes, int n_in,
                              void* d_out, int out_size)
{
    const float* q    = (const float*)d_in[0];
    const float* k    = (const float*)d_in[1];
    const float* v    = (const float*)d_in[2];
    const float* W    = (const float*)d_in[3];
    const float* bias = (const float*)d_in[4];
    float* out = (float*)d_out;

    const size_t sm3 = (size_t)(CC*CC + 32*XS_STRIDE) * sizeof(float);
    const size_t smB = (size_t)2 * 128 * BSTRIDE * sizeof(float);

    cudaFuncSetAttribute(projkv_kernel, cudaFuncAttributeMaxDynamicSharedMemorySize, PK_SMEM);
    cudaFuncSetAttribute(redmk_kernel,  cudaFuncAttributeMaxDynamicSharedMemorySize, RM_SMEM);
    cudaFuncSetAttribute(out_kernel,    cudaFuncAttributeMaxDynamicSharedMemorySize, (int)sm3);
    cudaFuncSetAttribute(brute_kernel,  cudaFuncAttributeMaxDynamicSharedMemorySize, (int)smB);

    projkv_kernel <<<NROWS/128*2, 256, PK_SMEM>>>(q, k, v, W, bias);
    redmk_kernel  <<<64, 256, RM_SMEM>>>(W, bias);
    den_kernel    <<<NROWS/8, 256>>>();
    compact_kernel<<<1, 256>>>();
    brute_kernel  <<<dim3(32, BB, 2), 256, smB>>>();
    out_kernel    <<<NROWS/128, 256, sm3>>>(out);
}

// round 17
// speedup vs baseline: 1.1222x; 1.1222x over previous
#include <cuda_runtime.h>
#include <cstdint>

#define BB 4
#define NN 4096
#define CC 128
#define NROWS (BB*NN)       // 16384
#define CHR 64              // rows per kv chunk
#define NCHUNK 64           // chunks per batch
#define TOTCHUNK (BB*NCHUNK)  // 256
#define XS_STRIDE 132
#define BSTRIDE 132

typedef unsigned long long u64;
__device__ __forceinline__ u64 pack2(float x, float y) {
    u64 r; asm("mov.b64 %0, {%1, %2};" : "=l"(r) : "f"(x), "f"(y)); return r;
}
__device__ __forceinline__ void unpack2(u64 v, float& x, float& y) {
    asm("mov.b64 {%0, %1}, %2;" : "=f"(x), "=f"(y) : "l"(v));
}
__device__ __forceinline__ u64 ffma2(u64 a, u64 b, u64 c) {
    u64 d; asm("fma.rn.f32x2 %0, %1, %2, %3;" : "=l"(d) : "l"(a), "l"(b), "l"(c)); return d;
}

// ---- scratch (device globals) ----
__device__ float  g_Q [NROWS*CC];
__device__ float  g_K [NROWS*CC];
__device__ float  g_Kh[NROWS*CC];
__device__ float  g_qnorm[NROWS];
__device__ float  g_knorm[NROWS];
__device__ float  g_Gpart[(size_t)TOTCHUNK*CC*CC];
__device__ double g_spart[TOTCHUNK*CC];
__device__ float  g_Mfin[BB*CC*CC];
__device__ double g_s[BB*CC];
__device__ float  g_sf[BB*CC];
__device__ double g_den[NROWS];
__device__ int    g_flag[NROWS];
__device__ int    g_bcount[BB];
__device__ int    g_list[BB*256];
__device__ double g_bpart[BB*256*32];

// ============================================================
// proj: Y = X @ W^T + b, f32x2, W staged in 32-k chunks (occ 2).
// z==0: q (+qn).  z==1: k (+kn, +k̂).     [r15-identical]
// ============================================================
__global__ void __launch_bounds__(256, 2) proj_kernel(
    const float* __restrict__ q_in, const float* __restrict__ k_in,
    const float* __restrict__ W, const float* __restrict__ bias)
{
    __shared__ float Wc[32*XS_STRIDE];
    __shared__ float Xs[32*XS_STRIDE];

    const int tid = threadIdx.x;
    const int tx  = tid & 15;
    const int ty  = tid >> 4;
    const int z   = blockIdx.y;
    const float* X = (z == 0) ? q_in : k_in;
    const int row0 = blockIdx.x * 128;

    u64 acc2[8][4];
    #pragma unroll
    for (int i = 0; i < 8; i++)
        #pragma unroll
        for (int jp = 0; jp < 4; jp++) acc2[i][jp] = 0ULL;

    for (int c0 = 0; c0 < CC; c0 += 32) {
        __syncthreads();
        for (int t = tid; t < 128*8; t += 256) {
            int r = t >> 3, cg = t & 7;
            float4 v = *(const float4*)(X + (size_t)(row0 + r)*CC + c0 + cg*4);
            Xs[(cg*4+0)*XS_STRIDE + r] = v.x;
            Xs[(cg*4+1)*XS_STRIDE + r] = v.y;
            Xs[(cg*4+2)*XS_STRIDE + r] = v.z;
            Xs[(cg*4+3)*XS_STRIDE + r] = v.w;
        }
        for (int t = tid; t < 128*8; t += 256) {
            int d = t >> 3, cg = t & 7;
            float4 w = *(const float4*)(W + (size_t)d*CC + c0 + cg*4);
            Wc[(cg*4+0)*XS_STRIDE + d] = w.x;
            Wc[(cg*4+1)*XS_STRIDE + d] = w.y;
            Wc[(cg*4+2)*XS_STRIDE + d] = w.z;
            Wc[(cg*4+3)*XS_STRIDE + d] = w.w;
        }
        __syncthreads();
        #pragma unroll 4
        for (int kk = 0; kk < 32; kk++) {
            float a[8];
            *(float4*)&a[0] = *(float4*)&Xs[kk*XS_STRIDE + ty*8];
            *(float4*)&a[4] = *(float4*)&Xs[kk*XS_STRIDE + ty*8 + 4];
            const ulonglong2 bv0 = *(ulonglong2*)&Wc[kk*XS_STRIDE + tx*8];
            const ulonglong2 bv1 = *(ulonglong2*)&Wc[kk*XS_STRIDE + tx*8 + 4];
            u64 b2[4] = {bv0.x, bv0.y, bv1.x, bv1.y};
            #pragma unroll
            for (int i = 0; i < 8; i++) {
                const u64 as = pack2(a[i], a[i]);
                #pragma unroll
                for (int jp = 0; jp < 4; jp++)
                    acc2[i][jp] = ffma2(as, b2[jp], acc2[i][jp]);
            }
        }
    }

    float acc[8][8];
    #pragma unroll
    for (int i = 0; i < 8; i++)
        #pragma unroll
        for (int jp = 0; jp < 4; jp++)
            unpack2(acc2[i][jp], acc[i][2*jp], acc[i][2*jp+1]);

    float bj[8];
    *(float4*)&bj[0] = *(const float4*)&bias[tx*8];
    *(float4*)&bj[4] = *(const float4*)&bias[tx*8 + 4];
    #pragma unroll
    for (int i = 0; i < 8; i++)
        #pragma unroll
        for (int j = 0; j < 8; j++) acc[i][j] += bj[j];

    float nrm[8];
    #pragma unroll
    for (int i = 0; i < 8; i++) {
        float sq = 0.f;
        #pragma unroll
        for (int j = 0; j < 8; j++) sq = fmaf(acc[i][j], acc[i][j], sq);
        #pragma unroll
        for (int off = 8; off; off >>= 1)
            sq += __shfl_xor_sync(0xffffffffu, sq, off, 16);
        nrm[i] = sqrtf(sq);
        if (tx == 0) {
            if (z == 0) g_qnorm[row0 + ty*8 + i] = nrm[i];
            else        g_knorm[row0 + ty*8 + i] = nrm[i];
        }
    }

    #pragma unroll
    for (int i = 0; i < 8; i++) {
        const size_t off = (size_t)(row0 + ty*8 + i)*CC + tx*8;
        if (z == 0) {
            *(float4*)(g_Q + off)     = *(float4*)&acc[i][0];
            *(float4*)(g_Q + off + 4) = *(float4*)&acc[i][4];
        } else {
            *(float4*)(g_K + off)     = *(float4*)&acc[i][0];
            *(float4*)(g_K + off + 4) = *(float4*)&acc[i][4];
            const float inv = 1.f / nrm[i];
            float4 o0, o1;
            o0.x = acc[i][0]*inv; o0.y = acc[i][1]*inv;
            o0.z = acc[i][2]*inv; o0.w = acc[i][3]*inv;
            o1.x = acc[i][4]*inv; o1.y = acc[i][5]*inv;
            o1.z = acc[i][6]*inv; o1.w = acc[i][7]*inv;
            *(float4*)(g_Kh + off)     = o0;
            *(float4*)(g_Kh + off + 4) = o1;
        }
    }
}

// ============================================================
// kv: partial G = K̂^T X_v over 64-row chunks (occ 2); s partials.
// ============================================================
__global__ void __launch_bounds__(256) kv_kernel(const float* __restrict__ v_in)
{
    extern __shared__ float sm[];
    float* Ks = sm;
    float* Vs = sm + CHR*CC;
    const int tid = threadIdx.x;
    const int tx  = tid & 15;
    const int ty  = tid >> 4;
    const int blk = blockIdx.x;
    const size_t base = (size_t)blk * CHR * CC;

    const float4* K4 = (const float4*)(g_Kh + base);
    const float4* V4 = (const float4*)(v_in + base);
    for (int t = tid; t < CHR*CC/4; t += 256) {
        ((float4*)Ks)[t] = K4[t];
        ((float4*)Vs)[t] = V4[t];
    }
    __syncthreads();

    u64 acc2[8][4];
    #pragma unroll
    for (int i = 0; i < 8; i++)
        #pragma unroll
        for (int jp = 0; jp < 4; jp++) acc2[i][jp] = 0ULL;

    #pragma unroll 4
    for (int n = 0; n < CHR; n++) {
        float a[8];
        *(float4*)&a[0] = *(float4*)&Ks[n*CC + ty*8];
        *(float4*)&a[4] = *(float4*)&Ks[n*CC + ty*8 + 4];
        const ulonglong2 bv0 = *(ulonglong2*)&Vs[n*CC + tx*8];
        const ulonglong2 bv1 = *(ulonglong2*)&Vs[n*CC + tx*8 + 4];
        u64 b2[4] = {bv0.x, bv0.y, bv1.x, bv1.y};
        #pragma unroll
        for (int i = 0; i < 8; i++) {
            const u64 as = pack2(a[i], a[i]);
            #pragma unroll
            for (int jp = 0; jp < 4; jp++)
                acc2[i][jp] = ffma2(as, b2[jp], acc2[i][jp]);
        }
    }

    if (tid < 128) {
        double s0 = 0.0, s1 = 0.0, s2 = 0.0, s3 = 0.0;
        #pragma unroll 4
        for (int n = 0; n < CHR; n += 4) {
            s0 += (double)Ks[(n+0)*CC + tid];
            s1 += (double)Ks[(n+1)*CC + tid];
            s2 += (double)Ks[(n+2)*CC + tid];
            s3 += (double)Ks[(n+3)*CC + tid];
        }
        g_spart[blk*CC + tid] = (s0 + s1) + (s2 + s3);
    }

    float* Gp = g_Gpart + (size_t)blk*CC*CC;
    #pragma unroll
    for (int i = 0; i < 8; i++) {
        float acc[8];
        #pragma unroll
        for (int jp = 0; jp < 4; jp++)
            unpack2(acc2[i][jp], acc[2*jp], acc[2*jp+1]);
        float* grow = Gp + (size_t)(ty*8 + i)*CC + tx*8;
        *(float4*)grow       = *(float4*)&acc[0];
        *(float4*)(grow + 4) = *(float4*)&acc[4];
    }
}

// ============================================================
// redmk (fused reduce + mk).
// ============================================================
#define RM_SMEM ((128*XS_STRIDE + 8*128 + 128) * 4 + 64*8 + 8*8)
__global__ void __launch_bounds__(256, 1) redmk_kernel(
    const float* __restrict__ W, const float* __restrict__ bias)
{
    extern __shared__ float sm[];
    float*  Wt   = sm;
    float*  Gs   = sm + 128*XS_STRIDE;
    float*  sb   = Gs + 8*128;
    double* sred = (double*)(sb + 128);
    double* sfin = sred + 64;

    const int tid = threadIdx.x;
    const int b   = blockIdx.x >> 4;
    const int c0  = (blockIdx.x & 15) * 8;

    {
        const int r  = tid >> 5;
        const int e4 = tid & 31;
        const int c  = c0 + r;
        float4 a0 = make_float4(0.f,0.f,0.f,0.f), a1 = a0, a2 = a0, a3 = a0;
        #pragma unroll 4
        for (int p = 0; p < NCHUNK; p += 4) {
            const size_t base = ((size_t)((b << 6) + p)) << 14;
            const size_t eoff = ((size_t)c << 7) + (e4 << 2);
            const float4 v0 = *(const float4*)&g_Gpart[base            + eoff];
            const float4 v1 = *(const float4*)&g_Gpart[base + (1u<<14) + eoff];
            const float4 v2 = *(const float4*)&g_Gpart[base + (2u<<14) + eoff];
            const float4 v3 = *(const float4*)&g_Gpart[base + (3u<<14) + eoff];
            a0.x += v0.x; a0.y += v0.y; a0.z += v0.z; a0.w += v0.w;
            a1.x += v1.x; a1.y += v1.y; a1.z += v1.z; a1.w += v1.w;
            a2.x += v2.x; a2.y += v2.y; a2.z += v2.z; a2.w += v2.w;
            a3.x += v3.x; a3.y += v3.y; a3.z += v3.z; a3.w += v3.w;
        }
        float4 a;
        a.x = (a0.x + a1.x) + (a2.x + a3.x);
        a.y = (a0.y + a1.y) + (a2.y + a3.y);
        a.z = (a0.z + a1.z) + (a2.z + a3.z);
        a.w = (a0.w + a1.w) + (a2.w + a3.w);
        *(float4*)&Gs[r*128 + e4*4] = a;
    }

    if (tid < 64) {
        const int cidx = tid >> 3;
        const int pg   = tid & 7;
        const int c    = c0 + cidx;
        double s = 0.0;
        #pragma unroll
        for (int j = 0; j < 8; j++)
            s += g_spart[((b << 6) + pg*8 + j)*CC + c];
        sred[cidx*8 + pg] = s;
    }

    for (int i = tid; i < CC*CC; i += 256) {
        int d = i >> 7, e = i & 127;
        Wt[e*XS_STRIDE + d] = W[i];
    }
    if (tid < 128) sb[tid] = bias[tid];
    __syncthreads();

    if (tid < 8) {
        double s = 0.0;
        #pragma unroll
        for (int pg = 0; pg < 8; pg++) s += sred[tid*8 + pg];
        sfin[tid] = s;
        g_s [b*CC + c0 + tid] = s;
        g_sf[b*CC + c0 + tid] = (float)s;
    }
    __syncthreads();

    if (tid < 128) {
        const int r  = tid >> 4;
        const int dg = tid & 15;
        float acc[8] = {};
        #pragma unroll 4
        for (int e = 0; e < 128; e++) {
            const float a = Gs[r*128 + e];
            float bb[8];
            *(float4*)&bb[0] = *(float4*)&Wt[e*XS_STRIDE + dg*8];
            *(float4*)&bb[4] = *(float4*)&Wt[e*XS_STRIDE + dg*8 + 4];
            #pragma unroll
            for (int j = 0; j < 8; j++)
                acc[j] = fmaf(a, bb[j], acc[j]);
        }
        const float sc = (float)sfin[r];
        float4 o0, o1;
        o0.x = fmaf(sc, sb[dg*8+0], acc[0]);
        o0.y = fmaf(sc, sb[dg*8+1], acc[1]);
        o0.z = fmaf(sc, sb[dg*8+2], acc[2]);
        o0.w = fmaf(sc, sb[dg*8+3], acc[3]);
        o1.x = fmaf(sc, sb[dg*8+4], acc[4]);
        o1.y = fmaf(sc, sb[dg*8+5], acc[5]);
        o1.z = fmaf(sc, sb[dg*8+6], acc[6]);
        o1.w = fmaf(sc, sb[dg*8+7], acc[7]);
        float* mrow = g_Mfin + (size_t)b*CC*CC + (size_t)(c0 + r)*CC + dg*8;
        *(float4*)mrow       = o0;
        *(float4*)(mrow + 4) = o1;
    }
}

// ============================================================
// den (fp32): den = q . s ; flag |den|/qn < 2.
// ============================================================
__global__ void __launch_bounds__(256) den_kernel()
{
    const int w = (blockIdx.x << 3) + (threadIdx.x >> 5);
    const int lane = threadIdx.x & 31;
    const int b = w >> 12;
    const float* qr = g_Q + (size_t)w*CC;
    const float* s  = g_sf + b*CC;
    float a0 = qr[lane      ] * s[lane      ];
    float a1 = qr[lane +  32] * s[lane +  32];
    float a2 = qr[lane +  64] * s[lane +  64];
    float a3 = qr[lane +  96] * s[lane +  96];
    float acc = (a0 + a1) + (a2 + a3);
    #pragma unroll
    for (int off = 16; off; off >>= 1)
        acc += __shfl_xor_sync(0xffffffffu, acc, off);
    if (lane == 0) {
        const float qn = g_qnorm[w];
        g_den[w] = (double)acc + 1e-8 * (double)qn;
        g_flag[w] = (fabsf(acc / qn) < 2.0f) ? 1 : 0;
    }
}

// ============================================================
// compact: ONE BLOCK PER BATCH (grid=4). Identical ascending-row
// ordering -> bit-identical slot assignment vs the serial version.
// ============================================================
__global__ void __launch_bounds__(256) compact_kernel()
{
    __shared__ int cnt[256];
    __shared__ int offs[256];
    const int b = blockIdx.x;
    const int t = threadIdx.x;
    const int base = b*NN + t*(NN/256);
    int c = 0;
    #pragma unroll
    for (int i = 0; i < NN/256; i++) c += g_flag[base + i];
    cnt[t] = c;
    __syncthreads();
    if (t == 0) {
        int run = 0;
        for (int u = 0; u < 256; u++) { offs[u] = run; run += cnt[u]; }
        g_bcount[b] = run < 256 ? run : 256;
    }
    __syncthreads();
    int o = offs[t];
    #pragma unroll
    for (int i = 0; i < NN/256; i++) {
        const int row = base + i;
        if (g_flag[row]) {
            if (o < 256) { g_list[b*256 + o] = row; g_flag[row] = b*256 + o + 1; }
            else         { g_flag[row] = 0; }
            o++;
        }
    }
}

// ============================================================
// brute: reference-replica den GEMM for flagged rows.
// ============================================================
__global__ void __launch_bounds__(256, 1) brute_kernel()
{
    extern __shared__ float sm[];
    float* Qs  = sm;
    float* Kst = sm + 128*BSTRIDE;
    __shared__ float qn_s[128], kn_s[128];

    const int chunk = blockIdx.x;
    const int b     = blockIdx.y;
    const int tile  = blockIdx.z;
    int cnt = g_bcount[b] - tile*128;
    if (cnt <= 0) return;
    if (cnt > 128) cnt = 128;

    const int tid = threadIdx.x;
    const int tx  = tid & 15;
    const int ty  = tid >> 4;
    const int wid = tid >> 5;
    const int lane = tid & 31;
    const int key0 = b*NN + chunk*128;

    for (int t = tid; t < 128*BSTRIDE; t += 256) Qs[t] = 0.f;
    __syncthreads();

    for (int r = wid; r < cnt; r += 8) {
        const int row = g_list[b*256 + tile*128 + r];
        const float* qr = g_Q + (size_t)row*CC;
        #pragma unroll
        for (int u = 0; u < 4; u++) {
            const int c = lane + u*32;
            Qs[c*BSTRIDE + r] = qr[c];
        }
        if (lane == 0) qn_s[r] = g_qnorm[row];
    }
    for (int r = cnt + tid; r < 128; r += 256) qn_s[r] = 1.f;

    for (int r = wid; r < 128; r += 8) {
        const float* kr = g_K + (size_t)(key0 + r)*CC;
        #pragma unroll
        for (int u = 0; u < 4; u++) {
            const int c = lane + u*32;
            Kst[c*BSTRIDE + r] = kr[c];
        }
        if (lane == 0) kn_s[r] = g_knorm[key0 + r];
    }
    __syncthreads();

    u64 acc2[8][4];
    #pragma unroll
    for (int i = 0; i < 8; i++)
        #pragma unroll
        for (int jp = 0; jp < 4; jp++) acc2[i][jp] = 0ULL;

    #pragma unroll 4
    for (int c = 0; c < 128; c++) {
        float a[8];
        *(float4*)&a[0] = *(float4*)&Qs[c*BSTRIDE + ty*8];
        *(float4*)&a[4] = *(float4*)&Qs[c*BSTRIDE + ty*8 + 4];
        const ulonglong2 bv0 = *(ulonglong2*)&Kst[c*BSTRIDE + tx*8];
        const ulonglong2 bv1 = *(ulonglong2*)&Kst[c*BSTRIDE + tx*8 + 4];
        u64 b2[4] = {bv0.x, bv0.y, bv1.x, bv1.y};
        #pragma unroll
        for (int i = 0; i < 8; i++) {
            const u64 as = pack2(a[i], a[i]);
            #pragma unroll
            for (int jp = 0; jp < 4; jp++)
                acc2[i][jp] = ffma2(as, b2[jp], acc2[i][jp]);
        }
    }

    #pragma unroll
    for (int i = 0; i < 8; i++) {
        float acc[8];
        #pragma unroll
        for (int jp = 0; jp < 4; jp++)
            unpack2(acc2[i][jp], acc[2*jp], acc[2*jp+1]);
        const float qn = qn_s[ty*8 + i];
        double dsum = 0.0;
        #pragma unroll
        for (int j = 0; j < 8; j++) {
            const float d = qn * kn_s[tx*8 + j] + 1e-8f;
            dsum += (double)(acc[j] / d);
        }
        #pragma unroll
        for (int off = 8; off; off >>= 1)
            dsum += __shfl_xor_sync(0xffffffffu, dsum, off, 16);
        if (tx == 0)
            g_bpart[((size_t)(b*256 + tile*128 + ty*8 + i))*32 + chunk] = dsum;
    }
}

// ============================================================
// out = (q @ M) / den; combine folded in.
// ============================================================
__global__ void __launch_bounds__(256, 2) out_kernel(float* __restrict__ out)
{
    extern __shared__ float sm[];
    float* Ms = sm;
    float* Xs = sm + CC*CC;

    const int tid = threadIdx.x;
    const int tx  = tid & 15;
    const int ty  = tid >> 4;
    const int b   = blockIdx.x >> 5;
    const int row0 = blockIdx.x * 128;

    const float4* M4 = (const float4*)(g_Mfin + (size_t)b*CC*CC);
    for (int t = tid; t < 4096; t += 256) ((float4*)Ms)[t] = M4[t];

    u64 acc2[8][4];
    #pragma unroll
    for (int i = 0; i < 8; i++)
        #pragma unroll
        for (int jp = 0; jp < 4; jp++) acc2[i][jp] = 0ULL;

    for (int c0 = 0; c0 < CC; c0 += 32) {
        __syncthreads();
        for (int t = tid; t < 128*8; t += 256) {
            int r = t >> 3, cg = t & 7;
            float4 v = *(const float4*)(g_Q + (size_t)(row0 + r)*CC + c0 + cg*4);
            Xs[(cg*4+0)*XS_STRIDE + r] = v.x;
            Xs[(cg*4+1)*XS_STRIDE + r] = v.y;
            Xs[(cg*4+2)*XS_STRIDE + r] = v.z;
            Xs[(cg*4+3)*XS_STRIDE + r] = v.w;
        }
        __syncthreads();
        #pragma unroll 4
        for (int kk = 0; kk < 32; kk++) {
            float a[8];
            *(float4*)&a[0] = *(float4*)&Xs[kk*XS_STRIDE + ty*8];
            *(float4*)&a[4] = *(float4*)&Xs[kk*XS_STRIDE + ty*8 + 4];
            const ulonglong2 bv0 = *(ulonglong2*)&Ms[(c0+kk)*CC + tx*8];
            const ulonglong2 bv1 = *(ulonglong2*)&Ms[(c0+kk)*CC + tx*8 + 4];
            u64 b2[4] = {bv0.x, bv0.y, bv1.x, bv1.y};
            #pragma unroll
            for (int i = 0; i < 8; i++) {
                const u64 as = pack2(a[i], a[i]);
                #pragma unroll
                for (int jp = 0; jp < 4; jp++)
                    acc2[i][jp] = ffma2(as, b2[jp], acc2[i][jp]);
            }
        }
    }

    #pragma unroll
    for (int i = 0; i < 8; i++) {
        float acc[8];
        #pragma unroll
        for (int jp = 0; jp < 4; jp++)
            unpack2(acc2[i][jp], acc[2*jp], acc[2*jp+1]);
        const int row = row0 + ty*8 + i;
        const int fl = g_flag[row];
        double den;
        if (fl > 0) {
            const int slot = fl - 1;
            double s = 0.0;
            #pragma unroll
            for (int c = 0; c < 32; c++)
                s += g_bpart[(size_t)slot*32 + c];
            den = (double)g_qnorm[row] * (s + 1e-8);
        } else {
            den = g_den[row];
        }
        const double inv = 1.0 / den;
        float4 o0, o1;
        o0.x = (float)(acc[0]*inv); o0.y = (float)(acc[1]*inv);
        o0.z = (float)(acc[2]*inv); o0.w = (float)(acc[3]*inv);
        o1.x = (float)(acc[4]*inv); o1.y = (float)(acc[5]*inv);
        o1.z = (float)(acc[6]*inv); o1.w = (float)(acc[7]*inv);
        float* orow = out + (size_t)row*CC + tx*8;
        *(float4*)orow       = o0;
        *(float4*)(orow + 4) = o1;
    }
}

// ============================================================
extern "C" void kernel_launch(void* const* d_in, const int* in_sizes, int n_in,
                              void* d_out, int out_size)
{
    const float* q    = (const float*)d_in[0];
    const float* k    = (const float*)d_in[1];
    const float* v    = (const float*)d_in[2];
    const float* W    = (const float*)d_in[3];
    const float* bias = (const float*)d_in[4];
    float* out = (float*)d_out;

    const size_t sm2 = (size_t)2 * CHR * CC * sizeof(float);    // 64KB
    const size_t sm3 = (size_t)(CC*CC + 32*XS_STRIDE) * sizeof(float);
    const size_t smB = (size_t)2 * 128 * BSTRIDE * sizeof(float);

    cudaFuncSetAttribute(kv_kernel,    cudaFuncAttributeMaxDynamicSharedMemorySize, (int)sm2);
    cudaFuncSetAttribute(redmk_kernel, cudaFuncAttributeMaxDynamicSharedMemorySize, RM_SMEM);
    cudaFuncSetAttribute(out_kernel,   cudaFuncAttributeMaxDynamicSharedMemorySize, (int)sm3);
    cudaFuncSetAttribute(brute_kernel, cudaFuncAttributeMaxDynamicSharedMemorySize, (int)smB);

    proj_kernel   <<<dim3(NROWS/128, 2), 256>>>(q, k, W, bias);
    kv_kernel     <<<TOTCHUNK, 256, sm2>>>(v);
    redmk_kernel  <<<64, 256, RM_SMEM>>>(W, bias);
    den_kernel    <<<NROWS/8, 256>>>();
    compact_kernel<<<BB, 256>>>();
    brute_kernel  <<<dim3(32, BB, 2), 256, smB>>>();
    out_kernel    <<<NROWS/128, 256, sm3>>>(out);
}